// round 2
// baseline (speedup 1.0000x reference)
#include <cuda_runtime.h>
#include <math.h>

#define S_LEN 4096
#define D_MODEL 1024
#define NHEAD 16
#define HD 64

// ---- scratch (device globals: allocation-free contract) ----
__device__ float g_qkv[(size_t)S_LEN * 3 * D_MODEL];   // 50.3 MB
__device__ float g_q[(size_t)NHEAD * S_LEN * HD];      // 16.8 MB
__device__ float g_k[(size_t)NHEAD * S_LEN * HD];
__device__ float g_v[(size_t)NHEAD * S_LEN * HD];
__device__ float g_o[(size_t)S_LEN * D_MODEL];         // 16.8 MB

// ============================================================
// Generic fp32 GEMM: C[M,N] = A[M,K] @ B[K,N], all row-major.
// 128x128 tile, Ktile=16, 256 threads, 8x8 per thread.
// Fragment ownership is strided (tx+16j / ty+16i) -> conflict-free LDS.
// ============================================================
__global__ void gemm_f32(const float* __restrict__ A, const float* __restrict__ B,
                         float* __restrict__ C, int M, int N, int K)
{
    __shared__ float As[16][128];   // k-major (transposed on store)
    __shared__ float Bs[16][128];

    const int t  = threadIdx.x;
    const int tx = t & 15;
    const int ty = t >> 4;
    const int bm = blockIdx.y * 128;
    const int bn = blockIdx.x * 128;

    float acc[8][8];
#pragma unroll
    for (int i = 0; i < 8; i++)
#pragma unroll
        for (int j = 0; j < 8; j++) acc[i][j] = 0.0f;

    const int ar = t >> 2;          // 0..63 (two passes of 64 rows)
    const int ak = (t & 3) * 4;     // 0,4,8,12
    const int br = t >> 5;          // 0..7  (two passes of 8 rows)
    const int bc = (t & 31) * 4;    // 0..124

    for (int k0 = 0; k0 < K; k0 += 16) {
#pragma unroll
        for (int p = 0; p < 2; p++) {
            float4 va = *(const float4*)(A + (size_t)(bm + ar + p * 64) * K + (k0 + ak));
            As[ak + 0][ar + p * 64] = va.x;
            As[ak + 1][ar + p * 64] = va.y;
            As[ak + 2][ar + p * 64] = va.z;
            As[ak + 3][ar + p * 64] = va.w;
            float4 vb = *(const float4*)(B + (size_t)(k0 + br + p * 8) * N + (bn + bc));
            *(float4*)&Bs[br + p * 8][bc] = vb;
        }
        __syncthreads();
#pragma unroll
        for (int kk = 0; kk < 16; kk++) {
            float a[8], b[8];
#pragma unroll
            for (int i = 0; i < 8; i++) a[i] = As[kk][ty + 16 * i];   // broadcast
#pragma unroll
            for (int j = 0; j < 8; j++) b[j] = Bs[kk][tx + 16 * j];   // 16 distinct banks
#pragma unroll
            for (int i = 0; i < 8; i++)
#pragma unroll
                for (int j = 0; j < 8; j++)
                    acc[i][j] = fmaf(a[i], b[j], acc[i][j]);
        }
        __syncthreads();
    }

#pragma unroll
    for (int i = 0; i < 8; i++) {
        const int row = bm + ty + 16 * i;
#pragma unroll
        for (int j = 0; j < 8; j++)
            C[(size_t)row * N + bn + tx + 16 * j] = acc[i][j];
    }
}

// ============================================================
// RoPE + split/scatter qkv -> head-major Q,K,V  [H][S][HD]
// ============================================================
__global__ void rope_split(const float* __restrict__ qkv,
                           const float* __restrict__ cosb,
                           const float* __restrict__ sinb)
{
    const int s = blockIdx.x;
    const float* row = qkv + (size_t)s * 3 * D_MODEL;
    for (int idx = threadIdx.x; idx < D_MODEL; idx += blockDim.x) {
        const int h = idx >> 6;
        const int d = idx & 63;
        const float c  = cosb[s * HD + d];
        const float sn = sinb[s * HD + d];
        const int base = h * HD + d;
        const int pair = (d < 32) ? base + 32 : base - 32;
        const float sgn = (d < 32) ? -1.0f : 1.0f;
        const size_t dst = ((size_t)h * S_LEN + s) * HD + d;

        float qv = row[base];
        float qr = sgn * row[pair];
        g_q[dst] = fmaf(qv, c, qr * sn);

        float kv = row[D_MODEL + base];
        float kr = sgn * row[D_MODEL + pair];
        g_k[dst] = fmaf(kv, c, kr * sn);

        g_v[dst] = row[2 * D_MODEL + base];
    }
}

// ============================================================
// Flash attention, fp32. BQ=BK=64, 256 threads (16x16 grid of
// 4x4 per-thread frags, strided ownership r=ty+16i, c=tx+16j).
// Dynamic smem layout (49,664 B):
//   Qt  [64 x 64], Qt[c*65 + r] (transposed, stride 65)  4160 f
//   KPs [64 x 65], K tile then aliased as P              4160 f
//   Vs  [64 x 64], stride 64                             4096 f
// Each block processes q-tiles {bx, 63-bx} -> constant 65 kv-tiles
// per block (perfect causal load balance).
// ============================================================
#define KST 65
#define FA_SMEM_FLOATS (64 * 65 + 64 * 65 + 64 * 64)
#define FA_SMEM_BYTES (FA_SMEM_FLOATS * 4)

__global__ void flash_attn()
{
    extern __shared__ float sm_[];
    float* Qt  = sm_;                       // stride KST (col-major: [c][r])
    float* KPs = sm_ + 64 * KST;            // stride KST (row-major)
    float* Vs  = sm_ + 2 * 64 * KST;        // stride 64  (row-major)

    const int t  = threadIdx.x;
    const int tx = t & 15;
    const int ty = t >> 4;
    const int h  = blockIdx.y;
    const float* Q = g_q + (size_t)h * S_LEN * HD;
    const float* K = g_k + (size_t)h * S_LEN * HD;
    const float* V = g_v + (size_t)h * S_LEN * HD;

    for (int pass = 0; pass < 2; pass++) {
        const int qt = pass ? (63 - (int)blockIdx.x) : (int)blockIdx.x;
        const int q0 = qt * 64;

        __syncthreads();  // previous pass fully done with smem
        for (int idx = t; idx < 64 * 64; idx += 256) {
            const int r = idx >> 6, c = idx & 63;
            Qt[c * KST + r] = Q[(size_t)(q0 + r) * HD + c];
        }

        float m[4], l[4], o[4][4];
#pragma unroll
        for (int i = 0; i < 4; i++) {
            m[i] = -1e30f; l[i] = 0.0f;
#pragma unroll
            for (int j = 0; j < 4; j++) o[i][j] = 0.0f;
        }

        for (int kt = 0; kt <= qt; kt++) {
            const int k0 = kt * 64;
            __syncthreads();  // prior P/V reads done; Qt visible (1st iter)
            for (int idx = t; idx < 64 * 64; idx += 256) {
                const int r = idx >> 6, c = idx & 63;
                KPs[r * KST + c] = K[(size_t)(k0 + r) * HD + c];
                Vs [r * 64  + c] = V[(size_t)(k0 + r) * HD + c];
            }
            __syncthreads();

            // S = Q K^T (4x4 per thread)
            float s_[4][4];
#pragma unroll
            for (int i = 0; i < 4; i++)
#pragma unroll
                for (int j = 0; j < 4; j++) s_[i][j] = 0.0f;

#pragma unroll 8
            for (int kk = 0; kk < 64; kk++) {
                float a[4], b[4];
#pragma unroll
                for (int i = 0; i < 4; i++) a[i] = Qt[kk * KST + ty + 16 * i];
#pragma unroll
                for (int j = 0; j < 4; j++) b[j] = KPs[(tx + 16 * j) * KST + kk];
#pragma unroll
                for (int i = 0; i < 4; i++)
#pragma unroll
                    for (int j = 0; j < 4; j++)
                        s_[i][j] = fmaf(a[i], b[j], s_[i][j]);
            }

            // scale + causal mask + online softmax (rows shared by 16 lanes)
#pragma unroll
            for (int i = 0; i < 4; i++) {
                const int rg = q0 + ty + 16 * i;
                float rm = -1e30f;
#pragma unroll
                for (int j = 0; j < 4; j++) {
                    const int cg = k0 + tx + 16 * j;
                    s_[i][j] = s_[i][j] * 0.125f + (cg > rg ? -1e9f : 0.0f);
                    rm = fmaxf(rm, s_[i][j]);
                }
#pragma unroll
                for (int off = 8; off > 0; off >>= 1)
                    rm = fmaxf(rm, __shfl_xor_sync(0xffffffffu, rm, off));
                const float mn = fmaxf(m[i], rm);
                const float sc = __expf(m[i] - mn);
                float rs = 0.0f;
#pragma unroll
                for (int j = 0; j < 4; j++) {
                    s_[i][j] = __expf(s_[i][j] - mn);
                    rs += s_[i][j];
                }
#pragma unroll
                for (int off = 8; off > 0; off >>= 1)
                    rs += __shfl_xor_sync(0xffffffffu, rs, off);
                l[i] = l[i] * sc + rs;
                m[i] = mn;
#pragma unroll
                for (int j = 0; j < 4; j++) o[i][j] *= sc;
            }

            __syncthreads();  // everyone done reading KPs as K
#pragma unroll
            for (int i = 0; i < 4; i++)
#pragma unroll
                for (int j = 0; j < 4; j++)
                    KPs[(ty + 16 * i) * KST + tx + 16 * j] = s_[i][j];
            __syncthreads();  // P visible

            // O += P V
#pragma unroll 8
            for (int cc = 0; cc < 64; cc++) {
                float pp[4], vv[4];
#pragma unroll
                for (int i = 0; i < 4; i++) pp[i] = KPs[(ty + 16 * i) * KST + cc];
#pragma unroll
                for (int j = 0; j < 4; j++) vv[j] = Vs[cc * 64 + tx + 16 * j];
#pragma unroll
                for (int i = 0; i < 4; i++)
#pragma unroll
                    for (int j = 0; j < 4; j++)
                        o[i][j] = fmaf(pp[i], vv[j], o[i][j]);
            }
        }

        // normalize + write O in [s, h*64+d] layout
#pragma unroll
        for (int i = 0; i < 4; i++) {
            const float inv = 1.0f / l[i];
            const int row = q0 + ty + 16 * i;
#pragma unroll
            for (int j = 0; j < 4; j++)
                g_o[(size_t)row * D_MODEL + h * HD + tx + 16 * j] = o[i][j] * inv;
        }
    }
}

// ============================================================
// launch
// ============================================================
extern "C" void kernel_launch(void* const* d_in, const int* in_sizes, int n_in,
                              void* d_out, int out_size)
{
    (void)in_sizes; (void)n_in; (void)out_size;
    const float* x    = (const float*)d_in[0];
    // d_in[1] = attn_mask: pure causal, applied analytically in flash_attn
    const float* cosb = (const float*)d_in[2];
    const float* sinb = (const float*)d_in[3];
    const float* Wqkv = (const float*)d_in[4];
    const float* Wout = (const float*)d_in[5];
    float* out = (float*)d_out;

    void* pqkv = nullptr;
    void* po   = nullptr;
    cudaGetSymbolAddress(&pqkv, g_qkv);
    cudaGetSymbolAddress(&po,   g_o);

    static int fa_attr_set = 0;
    if (!fa_attr_set) {
        cudaFuncSetAttribute(flash_attn,
                             cudaFuncAttributeMaxDynamicSharedMemorySize,
                             FA_SMEM_BYTES);
        fa_attr_set = 1;
    }

    // 1) qkv = x @ W_qkv   [4096,1024]@[1024,3072]
    gemm_f32<<<dim3(3 * D_MODEL / 128, S_LEN / 128), 256>>>(
        x, Wqkv, (float*)pqkv, S_LEN, 3 * D_MODEL, D_MODEL);

    // 2) RoPE + head-major split
    rope_split<<<S_LEN, 256>>>((const float*)pqkv, cosb, sinb);

    // 3) causal flash attention
    flash_attn<<<dim3(32, NHEAD), 256, FA_SMEM_BYTES>>>();

    // 4) out = O @ W_out   [4096,1024]@[1024,1024]
    gemm_f32<<<dim3(D_MODEL / 128, S_LEN / 128), 256>>>(
        (const float*)po, Wout, out, S_LEN, D_MODEL, D_MODEL);
}

// round 4
// speedup vs baseline: 3.5765x; 3.5765x over previous
#include <cuda_runtime.h>
#include <math.h>

#define S_LEN 4096
#define D_MODEL 1024
#define NHEAD 16
#define HD 64

// ---- scratch (device globals: allocation-free contract) ----
__device__ float g_qkv[(size_t)S_LEN * 3 * D_MODEL];
__device__ float g_q[(size_t)NHEAD * S_LEN * HD];
__device__ float g_k[(size_t)NHEAD * S_LEN * HD];
__device__ float g_v[(size_t)NHEAD * S_LEN * HD];
__device__ float g_o[(size_t)S_LEN * D_MODEL];

// ---- helpers ----
// cvt to tf32 requires a .b32 destination register
__device__ __forceinline__ float tf32r(float x) {
    unsigned u;
    asm("cvt.rna.tf32.f32 %0, %1;" : "=r"(u) : "f"(x));
    return __uint_as_float(u);
}
__device__ __forceinline__ unsigned fu(float x) { return __float_as_uint(x); }

// D = A(16x8 tf32, row) * B(8x8 tf32, col) + D, fp32 accum
__device__ __forceinline__ void mma8(float* c, unsigned a0, unsigned a1, unsigned a2,
                                     unsigned a3, unsigned b0, unsigned b1) {
    asm volatile(
        "mma.sync.aligned.m16n8k8.row.col.f32.tf32.tf32.f32 "
        "{%0,%1,%2,%3}, {%4,%5,%6,%7}, {%8,%9}, {%0,%1,%2,%3};\n"
        : "+f"(c[0]), "+f"(c[1]), "+f"(c[2]), "+f"(c[3])
        : "r"(a0), "r"(a1), "r"(a2), "r"(a3), "r"(b0), "r"(b1));
}

// ============================================================
// TF32 GEMM: C[M,N] = A[M,K] @ B[K,N], row-major.
// Block 128x128, Ktile 32, 8 warps (4m x 2n), warp tile 32x64.
// As[m][36]: frag bank = (4g+tg+kk)%32 -> conflict-free.
// Bs[k][136]: frag bank = (8tg+g)%32   -> conflict-free.
// ============================================================
__global__ void __launch_bounds__(256) gemm_tf32(const float* __restrict__ A,
                                                 const float* __restrict__ B,
                                                 float* __restrict__ C,
                                                 int M, int N, int K)
{
    __shared__ float As[128][36];
    __shared__ float Bs[32][136];

    const int t    = threadIdx.x;
    const int lane = t & 31;
    const int wid  = t >> 5;
    const int g    = lane >> 2;
    const int tg   = lane & 3;
    const int wm   = (wid >> 1) * 32;
    const int wn   = (wid & 1) * 64;
    const int bm   = blockIdx.y * 128;
    const int bn   = blockIdx.x * 128;

    const int arow = t >> 3;          // 0..31 (+32p)
    const int ak   = (t & 7) * 4;     // 0..28
    const int bk   = t >> 5;          // 0..7  (+8p)
    const int bn4  = (t & 31) * 4;    // 0..124

    float acc[2][8][4];
#pragma unroll
    for (int mt = 0; mt < 2; mt++)
#pragma unroll
        for (int nt = 0; nt < 8; nt++)
#pragma unroll
            for (int r = 0; r < 4; r++) acc[mt][nt][r] = 0.0f;

    for (int k0 = 0; k0 < K; k0 += 32) {
        __syncthreads();
#pragma unroll
        for (int p = 0; p < 4; p++) {
            float4 va = *(const float4*)(A + (size_t)(bm + arow + 32 * p) * K + (k0 + ak));
            *(float4*)&As[arow + 32 * p][ak] =
                make_float4(tf32r(va.x), tf32r(va.y), tf32r(va.z), tf32r(va.w));
            float4 vb = *(const float4*)(B + (size_t)(k0 + bk + 8 * p) * N + (bn + bn4));
            *(float4*)&Bs[bk + 8 * p][bn4] =
                make_float4(tf32r(vb.x), tf32r(vb.y), tf32r(vb.z), tf32r(vb.w));
        }
        __syncthreads();
#pragma unroll
        for (int ks = 0; ks < 4; ks++) {
            const int kk = ks * 8;
            unsigned aF[2][4];
#pragma unroll
            for (int mt = 0; mt < 2; mt++) {
                const int mb = wm + mt * 16;
                aF[mt][0] = fu(As[mb + g][kk + tg]);
                aF[mt][1] = fu(As[mb + g + 8][kk + tg]);
                aF[mt][2] = fu(As[mb + g][kk + tg + 4]);
                aF[mt][3] = fu(As[mb + g + 8][kk + tg + 4]);
            }
#pragma unroll
            for (int nt = 0; nt < 8; nt++) {
                unsigned b0 = fu(Bs[kk + tg][wn + nt * 8 + g]);
                unsigned b1 = fu(Bs[kk + tg + 4][wn + nt * 8 + g]);
                mma8(acc[0][nt], aF[0][0], aF[0][1], aF[0][2], aF[0][3], b0, b1);
                mma8(acc[1][nt], aF[1][0], aF[1][1], aF[1][2], aF[1][3], b0, b1);
            }
        }
    }

#pragma unroll
    for (int mt = 0; mt < 2; mt++)
#pragma unroll
        for (int nt = 0; nt < 8; nt++) {
            const int row = bm + wm + mt * 16 + g;
            const int col = bn + wn + nt * 8 + 2 * tg;
            *(float2*)(C + (size_t)row * N + col) =
                make_float2(acc[mt][nt][0], acc[mt][nt][1]);
            *(float2*)(C + (size_t)(row + 8) * N + col) =
                make_float2(acc[mt][nt][2], acc[mt][nt][3]);
        }
}

// ============================================================
// RoPE + split/scatter qkv -> head-major Q,K,V  [H][S][HD]
// ============================================================
__global__ void rope_split(const float* __restrict__ qkv,
                           const float* __restrict__ cosb,
                           const float* __restrict__ sinb)
{
    const int s = blockIdx.x;
    const float* row = qkv + (size_t)s * 3 * D_MODEL;
    for (int idx = threadIdx.x; idx < D_MODEL; idx += blockDim.x) {
        const int h = idx >> 6;
        const int d = idx & 63;
        const float c  = cosb[s * HD + d];
        const float sn = sinb[s * HD + d];
        const int base = h * HD + d;
        const int pair = (d < 32) ? base + 32 : base - 32;
        const float sgn = (d < 32) ? -1.0f : 1.0f;
        const size_t dst = ((size_t)h * S_LEN + s) * HD + d;

        float qv = row[base];
        float qr = sgn * row[pair];
        g_q[dst] = fmaf(qv, c, qr * sn);

        float kv = row[D_MODEL + base];
        float kr = sgn * row[D_MODEL + pair];
        g_k[dst] = fmaf(kv, c, kr * sn);

        g_v[dst] = row[2 * D_MODEL + base];
    }
}

// ============================================================
// Flash attention, tf32 tensor cores. BQ=BK=64, 4 warps.
// Warp w owns q-rows [w*16, w*16+16).  S/O accum in mma frags.
// Qs[m][68], Ks[kv][68]: frag bank 4g+tg  (conflict-free)
// Vs[kv][72]: frag bank 8tg+g             (conflict-free)
// P stays in registers: S-frag -> A-frag via quad shfl.
// Pair scheme: block bx does q-tiles {bx, 63-bx} -> 65 kv tiles.
// ============================================================
#define QSS 68
#define KSS 68
#define VSS 72
#define FA_SMEM_BYTES ((64 * QSS + 64 * KSS + 64 * VSS) * 4)

__global__ void __launch_bounds__(128) flash_attn_tc()
{
    extern __shared__ float sm_[];
    float* Qs = sm_;
    float* Ks = sm_ + 64 * QSS;
    float* Vs = sm_ + 64 * QSS + 64 * KSS;

    const int t    = threadIdx.x;
    const int lane = t & 31;
    const int w    = t >> 5;
    const int g    = lane >> 2;
    const int tg   = lane & 3;
    const int h    = blockIdx.y;

    const float* Q = g_q + (size_t)h * S_LEN * HD;
    const float* K = g_k + (size_t)h * S_LEN * HD;
    const float* V = g_v + (size_t)h * S_LEN * HD;

    // P-regather shuffle sources (within quad rows)
    const int qb  = lane & ~3;
    const int sA  = qb + (tg >> 1);       // cols tg
    const int sB  = qb + 2 + (tg >> 1);   // cols tg+4
    const bool odd = (tg & 1) != 0;

    for (int pass = 0; pass < 2; pass++) {
        const int qt = pass ? (63 - (int)blockIdx.x) : (int)blockIdx.x;
        const int q0 = qt * 64;

        __syncthreads();   // prior pass done with smem
        for (int i = t; i < 1024; i += 128) {
            const int m = i >> 4, d4 = (i & 15) * 4;
            float4 v = *(const float4*)(Q + (size_t)(q0 + m) * HD + d4);
            *(float4*)&Qs[m * QSS + d4] =
                make_float4(tf32r(v.x), tf32r(v.y), tf32r(v.z), tf32r(v.w));
        }

        float mx0 = -1e30f, mx1 = -1e30f, l0 = 0.0f, l1 = 0.0f;
        float o[8][4];
#pragma unroll
        for (int nt = 0; nt < 8; nt++)
#pragma unroll
            for (int r = 0; r < 4; r++) o[nt][r] = 0.0f;

        for (int kt = 0; kt <= qt; kt++) {
            const int k0 = kt * 64;
            __syncthreads();   // prior iter PV done (and Qs visible on iter 0)
            for (int i = t; i < 1024; i += 128) {
                const int r = i >> 4, d4 = (i & 15) * 4;
                float4 kv4 = *(const float4*)(K + (size_t)(k0 + r) * HD + d4);
                *(float4*)&Ks[r * KSS + d4] =
                    make_float4(tf32r(kv4.x), tf32r(kv4.y), tf32r(kv4.z), tf32r(kv4.w));
                float4 vv4 = *(const float4*)(V + (size_t)(k0 + r) * HD + d4);
                *(float4*)&Vs[r * VSS + d4] =
                    make_float4(tf32r(vv4.x), tf32r(vv4.y), tf32r(vv4.z), tf32r(vv4.w));
            }
            __syncthreads();

            // ---- S = Q K^T ----
            float s[8][4];
#pragma unroll
            for (int nt = 0; nt < 8; nt++)
#pragma unroll
                for (int r = 0; r < 4; r++) s[nt][r] = 0.0f;

#pragma unroll
            for (int ks = 0; ks < 8; ks++) {
                const int d0 = ks * 8;
                const unsigned a0 = fu(Qs[(w * 16 + g) * QSS + d0 + tg]);
                const unsigned a1 = fu(Qs[(w * 16 + g + 8) * QSS + d0 + tg]);
                const unsigned a2 = fu(Qs[(w * 16 + g) * QSS + d0 + tg + 4]);
                const unsigned a3 = fu(Qs[(w * 16 + g + 8) * QSS + d0 + tg + 4]);
#pragma unroll
                for (int nt = 0; nt < 8; nt++) {
                    const unsigned b0 = fu(Ks[(nt * 8 + g) * KSS + d0 + tg]);
                    const unsigned b1 = fu(Ks[(nt * 8 + g) * KSS + d0 + tg + 4]);
                    mma8(s[nt], a0, a1, a2, a3, b0, b1);
                }
            }

            // ---- scale + causal mask ----
            const int r0 = q0 + w * 16 + g;
            const int r1 = r0 + 8;
#pragma unroll
            for (int nt = 0; nt < 8; nt++) {
                const int c0 = k0 + nt * 8 + 2 * tg;
                const int c1 = c0 + 1;
                s[nt][0] = (c0 > r0) ? -1e9f : s[nt][0] * 0.125f;
                s[nt][1] = (c1 > r0) ? -1e9f : s[nt][1] * 0.125f;
                s[nt][2] = (c0 > r1) ? -1e9f : s[nt][2] * 0.125f;
                s[nt][3] = (c1 > r1) ? -1e9f : s[nt][3] * 0.125f;
            }

            // ---- online softmax (rows r0 across quad lanes) ----
            float rm0 = -1e30f, rm1 = -1e30f;
#pragma unroll
            for (int nt = 0; nt < 8; nt++) {
                rm0 = fmaxf(rm0, fmaxf(s[nt][0], s[nt][1]));
                rm1 = fmaxf(rm1, fmaxf(s[nt][2], s[nt][3]));
            }
#pragma unroll
            for (int off = 1; off <= 2; off <<= 1) {
                rm0 = fmaxf(rm0, __shfl_xor_sync(0xffffffffu, rm0, off));
                rm1 = fmaxf(rm1, __shfl_xor_sync(0xffffffffu, rm1, off));
            }
            const float mn0 = fmaxf(mx0, rm0);
            const float mn1 = fmaxf(mx1, rm1);
            const float sc0 = __expf(mx0 - mn0);
            const float sc1 = __expf(mx1 - mn1);
            float rs0 = 0.0f, rs1 = 0.0f;
#pragma unroll
            for (int nt = 0; nt < 8; nt++) {
                s[nt][0] = tf32r(__expf(s[nt][0] - mn0));
                s[nt][1] = tf32r(__expf(s[nt][1] - mn0));
                s[nt][2] = tf32r(__expf(s[nt][2] - mn1));
                s[nt][3] = tf32r(__expf(s[nt][3] - mn1));
                rs0 += s[nt][0] + s[nt][1];
                rs1 += s[nt][2] + s[nt][3];
            }
#pragma unroll
            for (int off = 1; off <= 2; off <<= 1) {
                rs0 += __shfl_xor_sync(0xffffffffu, rs0, off);
                rs1 += __shfl_xor_sync(0xffffffffu, rs1, off);
            }
            l0 = l0 * sc0 + rs0;
            l1 = l1 * sc1 + rs1;
            mx0 = mn0;
            mx1 = mn1;
#pragma unroll
            for (int nt = 0; nt < 8; nt++) {
                o[nt][0] *= sc0; o[nt][1] *= sc0;
                o[nt][2] *= sc1; o[nt][3] *= sc1;
            }

            // ---- O += P V : regather P frags via quad shfl ----
#pragma unroll
            for (int j = 0; j < 8; j++) {
                const float v00 = __shfl_sync(0xffffffffu, s[j][0], sA);
                const float v01 = __shfl_sync(0xffffffffu, s[j][1], sA);
                const float v10 = __shfl_sync(0xffffffffu, s[j][2], sA);
                const float v11 = __shfl_sync(0xffffffffu, s[j][3], sA);
                const float w00 = __shfl_sync(0xffffffffu, s[j][0], sB);
                const float w01 = __shfl_sync(0xffffffffu, s[j][1], sB);
                const float w10 = __shfl_sync(0xffffffffu, s[j][2], sB);
                const float w11 = __shfl_sync(0xffffffffu, s[j][3], sB);
                const unsigned a0 = fu(odd ? v01 : v00);   // P[g   ][8j+tg  ]
                const unsigned a1 = fu(odd ? v11 : v10);   // P[g+8 ][8j+tg  ]
                const unsigned a2 = fu(odd ? w01 : w00);   // P[g   ][8j+tg+4]
                const unsigned a3 = fu(odd ? w11 : w10);   // P[g+8 ][8j+tg+4]
                const int kk = j * 8;
#pragma unroll
                for (int nt = 0; nt < 8; nt++) {
                    const unsigned b0 = fu(Vs[(kk + tg) * VSS + nt * 8 + g]);
                    const unsigned b1 = fu(Vs[(kk + tg + 4) * VSS + nt * 8 + g]);
                    mma8(o[nt], a0, a1, a2, a3, b0, b1);
                }
            }
        }

        // ---- normalize + write O[s, h*64+d] ----
        const float inv0 = 1.0f / l0;
        const float inv1 = 1.0f / l1;
        const int r0 = q0 + w * 16 + g;
#pragma unroll
        for (int nt = 0; nt < 8; nt++) {
            const int col = h * HD + nt * 8 + 2 * tg;
            *(float2*)(g_o + (size_t)r0 * D_MODEL + col) =
                make_float2(o[nt][0] * inv0, o[nt][1] * inv0);
            *(float2*)(g_o + (size_t)(r0 + 8) * D_MODEL + col) =
                make_float2(o[nt][2] * inv1, o[nt][3] * inv1);
        }
    }
}

// ============================================================
// launch
// ============================================================
extern "C" void kernel_launch(void* const* d_in, const int* in_sizes, int n_in,
                              void* d_out, int out_size)
{
    (void)in_sizes; (void)n_in; (void)out_size;
    const float* x    = (const float*)d_in[0];
    // d_in[1] = attn_mask: pure causal, handled analytically
    const float* cosb = (const float*)d_in[2];
    const float* sinb = (const float*)d_in[3];
    const float* Wqkv = (const float*)d_in[4];
    const float* Wout = (const float*)d_in[5];
    float* out = (float*)d_out;

    void* pqkv = nullptr;
    void* po   = nullptr;
    cudaGetSymbolAddress(&pqkv, g_qkv);
    cudaGetSymbolAddress(&po,   g_o);

    static int attr_set = 0;
    if (!attr_set) {
        cudaFuncSetAttribute(flash_attn_tc,
                             cudaFuncAttributeMaxDynamicSharedMemorySize,
                             FA_SMEM_BYTES);
        attr_set = 1;
    }

    // 1) qkv = x @ W_qkv   [4096,1024]@[1024,3072]
    gemm_tf32<<<dim3(3 * D_MODEL / 128, S_LEN / 128), 256>>>(
        x, Wqkv, (float*)pqkv, S_LEN, 3 * D_MODEL, D_MODEL);

    // 2) RoPE + head-major split
    rope_split<<<S_LEN, 256>>>((const float*)pqkv, cosb, sinb);

    // 3) causal flash attention (tensor cores)
    flash_attn_tc<<<dim3(32, NHEAD), 128, FA_SMEM_BYTES>>>();

    // 4) out = O @ W_out   [4096,1024]@[1024,1024]
    gemm_tf32<<<dim3(D_MODEL / 128, S_LEN / 128), 256>>>(
        (const float*)po, Wout, out, S_LEN, D_MODEL, D_MODEL);
}

// round 6
// speedup vs baseline: 4.0720x; 1.1385x over previous
#include <cuda_runtime.h>
#include <math.h>

#define S_LEN 4096
#define D_MODEL 1024
#define NHEAD 16
#define HD 64

// ---- scratch (device globals: allocation-free contract) ----
__device__ float g_qkv[(size_t)S_LEN * 3 * D_MODEL];
__device__ float g_q[(size_t)NHEAD * S_LEN * HD];
__device__ float g_k[(size_t)NHEAD * S_LEN * HD];
__device__ float g_v[(size_t)NHEAD * S_LEN * HD];
__device__ float g_o[(size_t)S_LEN * D_MODEL];

// ---- helpers ----
__device__ __forceinline__ float tf32r(float x) {
    unsigned u;
    asm("cvt.rna.tf32.f32 %0, %1;" : "=r"(u) : "f"(x));
    return __uint_as_float(u);
}
__device__ __forceinline__ unsigned fu(float x) { return __float_as_uint(x); }

__device__ __forceinline__ void mma8(float* c, unsigned a0, unsigned a1, unsigned a2,
                                     unsigned a3, unsigned b0, unsigned b1) {
    asm volatile(
        "mma.sync.aligned.m16n8k8.row.col.f32.tf32.tf32.f32 "
        "{%0,%1,%2,%3}, {%4,%5,%6,%7}, {%8,%9}, {%0,%1,%2,%3};\n"
        : "+f"(c[0]), "+f"(c[1]), "+f"(c[2]), "+f"(c[3])
        : "r"(a0), "r"(a1), "r"(a2), "r"(a3), "r"(b0), "r"(b1));
}

__device__ __forceinline__ void cpa16(float* dst_smem, const float* src) {
    unsigned d = (unsigned)__cvta_generic_to_shared(dst_smem);
    asm volatile("cp.async.cg.shared.global [%0], [%1], 16;\n" :: "r"(d), "l"(src));
}
__device__ __forceinline__ void cpa_commit() {
    asm volatile("cp.async.commit_group;\n");
}
template <int N>
__device__ __forceinline__ void cpa_wait() {
    asm volatile("cp.async.wait_group %0;\n" :: "n"(N));
}

// ============================================================
// TF32 GEMM (unchanged from R4): C = A @ B, 128x128 tile.
// ============================================================
__global__ void __launch_bounds__(256) gemm_tf32(const float* __restrict__ A,
                                                 const float* __restrict__ B,
                                                 float* __restrict__ C,
                                                 int M, int N, int K)
{
    __shared__ float As[128][36];
    __shared__ float Bs[32][136];

    const int t    = threadIdx.x;
    const int lane = t & 31;
    const int wid  = t >> 5;
    const int g    = lane >> 2;
    const int tg   = lane & 3;
    const int wm   = (wid >> 1) * 32;
    const int wn   = (wid & 1) * 64;
    const int bm   = blockIdx.y * 128;
    const int bn   = blockIdx.x * 128;

    const int arow = t >> 3;
    const int ak   = (t & 7) * 4;
    const int bk   = t >> 5;
    const int bn4  = (t & 31) * 4;

    float acc[2][8][4];
#pragma unroll
    for (int mt = 0; mt < 2; mt++)
#pragma unroll
        for (int nt = 0; nt < 8; nt++)
#pragma unroll
            for (int r = 0; r < 4; r++) acc[mt][nt][r] = 0.0f;

    for (int k0 = 0; k0 < K; k0 += 32) {
        __syncthreads();
#pragma unroll
        for (int p = 0; p < 4; p++) {
            float4 va = *(const float4*)(A + (size_t)(bm + arow + 32 * p) * K + (k0 + ak));
            *(float4*)&As[arow + 32 * p][ak] =
                make_float4(tf32r(va.x), tf32r(va.y), tf32r(va.z), tf32r(va.w));
            float4 vb = *(const float4*)(B + (size_t)(k0 + bk + 8 * p) * N + (bn + bn4));
            *(float4*)&Bs[bk + 8 * p][bn4] =
                make_float4(tf32r(vb.x), tf32r(vb.y), tf32r(vb.z), tf32r(vb.w));
        }
        __syncthreads();
#pragma unroll
        for (int ks = 0; ks < 4; ks++) {
            const int kk = ks * 8;
            unsigned aF[2][4];
#pragma unroll
            for (int mt = 0; mt < 2; mt++) {
                const int mb = wm + mt * 16;
                aF[mt][0] = fu(As[mb + g][kk + tg]);
                aF[mt][1] = fu(As[mb + g + 8][kk + tg]);
                aF[mt][2] = fu(As[mb + g][kk + tg + 4]);
                aF[mt][3] = fu(As[mb + g + 8][kk + tg + 4]);
            }
#pragma unroll
            for (int nt = 0; nt < 8; nt++) {
                unsigned b0 = fu(Bs[kk + tg][wn + nt * 8 + g]);
                unsigned b1 = fu(Bs[kk + tg + 4][wn + nt * 8 + g]);
                mma8(acc[0][nt], aF[0][0], aF[0][1], aF[0][2], aF[0][3], b0, b1);
                mma8(acc[1][nt], aF[1][0], aF[1][1], aF[1][2], aF[1][3], b0, b1);
            }
        }
    }

#pragma unroll
    for (int mt = 0; mt < 2; mt++)
#pragma unroll
        for (int nt = 0; nt < 8; nt++) {
            const int row = bm + wm + mt * 16 + g;
            const int col = bn + wn + nt * 8 + 2 * tg;
            *(float2*)(C + (size_t)row * N + col) =
                make_float2(acc[mt][nt][0], acc[mt][nt][1]);
            *(float2*)(C + (size_t)(row + 8) * N + col) =
                make_float2(acc[mt][nt][2], acc[mt][nt][3]);
        }
}

// ============================================================
// RoPE + split -> head-major Q,K,V. Outputs PRE-ROUNDED to tf32
// so the attention kernel can cp.async raw bytes losslessly.
// ============================================================
__global__ void rope_split(const float* __restrict__ qkv,
                           const float* __restrict__ cosb,
                           const float* __restrict__ sinb)
{
    const int s = blockIdx.x;
    const float* row = qkv + (size_t)s * 3 * D_MODEL;
    for (int idx = threadIdx.x; idx < D_MODEL; idx += blockDim.x) {
        const int h = idx >> 6;
        const int d = idx & 63;
        const float c  = cosb[s * HD + d];
        const float sn = sinb[s * HD + d];
        const int base = h * HD + d;
        const int pair = (d < 32) ? base + 32 : base - 32;
        const float sgn = (d < 32) ? -1.0f : 1.0f;
        const size_t dst = ((size_t)h * S_LEN + s) * HD + d;

        g_q[dst] = tf32r(fmaf(row[base], c, sgn * row[pair] * sn));
        g_k[dst] = tf32r(fmaf(row[D_MODEL + base], c, sgn * row[D_MODEL + pair] * sn));
        g_v[dst] = tf32r(row[2 * D_MODEL + base]);
    }
}

// ============================================================
// Flash attention v2: BQ=128, 4 warps of m32 x n64, BK=64.
// Q A-frags register-resident (loaded once per q-tile).
// K/V double-buffered in smem via cp.async (pre-rounded tf32).
// P stays in registers (quad shfl regather).
// Pair scheme: block bx does q-tiles {bx, 31-bx} -> 68 kv-tiles.
// smem: K 2x64x68 + V 2x64x72 = 71,680 B -> 2 CTA/SM.
// ============================================================
#define KSS 68
#define VSS 72
#define FA_SMEM_BYTES ((2 * 64 * KSS + 2 * 64 * VSS) * 4)

__global__ void __launch_bounds__(128) flash_attn_tc2()
{
    extern __shared__ float sm_[];
    float* Kb0 = sm_;
    float* Kb1 = sm_ + 64 * KSS;
    float* Vb0 = sm_ + 2 * 64 * KSS;
    float* Vb1 = sm_ + 2 * 64 * KSS + 64 * VSS;

    const int t    = threadIdx.x;
    const int lane = t & 31;
    const int w    = t >> 5;
    const int g    = lane >> 2;
    const int tg   = lane & 3;
    const int h    = blockIdx.y;
    const int wm   = w * 32;

    const float* Q = g_q + (size_t)h * S_LEN * HD;
    const float* K = g_k + (size_t)h * S_LEN * HD;
    const float* V = g_v + (size_t)h * S_LEN * HD;

    // P-regather shuffle sources (within quad)
    const int qb  = lane & ~3;
    const int sA  = qb + (tg >> 1);
    const int sB  = qb + 2 + (tg >> 1);
    const bool odd = (tg & 1) != 0;

    const int lr = t >> 4;          // 0..7  loader row base
    const int ld4 = (t & 15) * 4;   // 0..60 loader col

    for (int pass = 0; pass < 2; pass++) {
        const int qt = pass ? (31 - (int)blockIdx.x) : (int)blockIdx.x;
        const int q0 = qt * 128;
        const int ntile = 2 * qt + 2;

        // ---- Q fragments -> registers (reused across all kv tiles) ----
        unsigned qf[2][8][4];
#pragma unroll
        for (int mt = 0; mt < 2; mt++) {
            const float* qr = Q + (size_t)(q0 + wm + 16 * mt + g) * HD;
#pragma unroll
            for (int ks = 0; ks < 8; ks++) {
                qf[mt][ks][0] = fu(qr[8 * ks + tg]);
                qf[mt][ks][1] = fu(qr[512 + 8 * ks + tg]);      // row +8
                qf[mt][ks][2] = fu(qr[8 * ks + tg + 4]);
                qf[mt][ks][3] = fu(qr[512 + 8 * ks + tg + 4]);
            }
        }

        float mx[2][2], l[2][2];
        float o[2][8][4];
#pragma unroll
        for (int mt = 0; mt < 2; mt++) {
            mx[mt][0] = mx[mt][1] = -1e30f;
            l[mt][0] = l[mt][1] = 0.0f;
#pragma unroll
            for (int nt = 0; nt < 8; nt++)
#pragma unroll
                for (int r = 0; r < 4; r++) o[mt][nt][r] = 0.0f;
        }

        // ---- prefetch tile 0 into buffer 0 ----
        {
            const float* Ksrc = K;   // k0 = 0
            const float* Vsrc = V;
#pragma unroll
            for (int p = 0; p < 8; p++) {
                const int r = lr + 8 * p;
                cpa16(&Kb0[r * KSS + ld4], Ksrc + (size_t)r * HD + ld4);
                cpa16(&Vb0[r * VSS + ld4], Vsrc + (size_t)r * HD + ld4);
            }
            cpa_commit();
        }

        const int wrow_max = q0 + wm + 31;   // last q-row this warp owns

        for (int kt = 0; kt < ntile; kt++) {
            const int k0 = kt * 64;
            float* Kc = (kt & 1) ? Kb1 : Kb0;
            float* Vc = (kt & 1) ? Vb1 : Vb0;

            // prefetch next tile into the other buffer
            if (kt + 1 < ntile) {
                float* Kn = (kt & 1) ? Kb0 : Kb1;
                float* Vn = (kt & 1) ? Vb0 : Vb1;
                const float* Ksrc = K + (size_t)(k0 + 64) * HD;
                const float* Vsrc = V + (size_t)(k0 + 64) * HD;
#pragma unroll
                for (int p = 0; p < 8; p++) {
                    const int r = lr + 8 * p;
                    cpa16(&Kn[r * KSS + ld4], Ksrc + (size_t)r * HD + ld4);
                    cpa16(&Vn[r * VSS + ld4], Vsrc + (size_t)r * HD + ld4);
                }
            }
            cpa_commit();
            cpa_wait<1>();      // tile kt resident
            __syncthreads();

            if (k0 <= wrow_max) {   // warp-uniform causal skip
                // ---- S = Q K^T ----
                float s[2][8][4];
#pragma unroll
                for (int mt = 0; mt < 2; mt++)
#pragma unroll
                    for (int nt = 0; nt < 8; nt++)
#pragma unroll
                        for (int r = 0; r < 4; r++) s[mt][nt][r] = 0.0f;

#pragma unroll
                for (int ks = 0; ks < 8; ks++) {
                    const int d0 = ks * 8;
#pragma unroll
                    for (int nt = 0; nt < 8; nt++) {
                        const unsigned b0 = fu(Kc[(nt * 8 + g) * KSS + d0 + tg]);
                        const unsigned b1 = fu(Kc[(nt * 8 + g) * KSS + d0 + tg + 4]);
                        mma8(s[0][nt], qf[0][ks][0], qf[0][ks][1], qf[0][ks][2], qf[0][ks][3], b0, b1);
                        mma8(s[1][nt], qf[1][ks][0], qf[1][ks][1], qf[1][ks][2], qf[1][ks][3], b0, b1);
                    }
                }

                // ---- scale + mask + online softmax ----
#pragma unroll
                for (int mt = 0; mt < 2; mt++) {
                    const int r0 = q0 + wm + 16 * mt + g;
                    const int r1 = r0 + 8;
                    float rm0 = -1e30f, rm1 = -1e30f;
#pragma unroll
                    for (int nt = 0; nt < 8; nt++) {
                        const int c0 = k0 + nt * 8 + 2 * tg;
                        const int c1 = c0 + 1;
                        s[mt][nt][0] = (c0 > r0) ? -1e9f : s[mt][nt][0] * 0.125f;
                        s[mt][nt][1] = (c1 > r0) ? -1e9f : s[mt][nt][1] * 0.125f;
                        s[mt][nt][2] = (c0 > r1) ? -1e9f : s[mt][nt][2] * 0.125f;
                        s[mt][nt][3] = (c1 > r1) ? -1e9f : s[mt][nt][3] * 0.125f;
                        rm0 = fmaxf(rm0, fmaxf(s[mt][nt][0], s[mt][nt][1]));
                        rm1 = fmaxf(rm1, fmaxf(s[mt][nt][2], s[mt][nt][3]));
                    }
#pragma unroll
                    for (int off = 1; off <= 2; off <<= 1) {
                        rm0 = fmaxf(rm0, __shfl_xor_sync(0xffffffffu, rm0, off));
                        rm1 = fmaxf(rm1, __shfl_xor_sync(0xffffffffu, rm1, off));
                    }
                    const float mn0 = fmaxf(mx[mt][0], rm0);
                    const float mn1 = fmaxf(mx[mt][1], rm1);
                    const float sc0 = __expf(mx[mt][0] - mn0);
                    const float sc1 = __expf(mx[mt][1] - mn1);
                    float rs0 = 0.0f, rs1 = 0.0f;
#pragma unroll
                    for (int nt = 0; nt < 8; nt++) {
                        s[mt][nt][0] = tf32r(__expf(s[mt][nt][0] - mn0));
                        s[mt][nt][1] = tf32r(__expf(s[mt][nt][1] - mn0));
                        s[mt][nt][2] = tf32r(__expf(s[mt][nt][2] - mn1));
                        s[mt][nt][3] = tf32r(__expf(s[mt][nt][3] - mn1));
                        rs0 += s[mt][nt][0] + s[mt][nt][1];
                        rs1 += s[mt][nt][2] + s[mt][nt][3];
                    }
#pragma unroll
                    for (int off = 1; off <= 2; off <<= 1) {
                        rs0 += __shfl_xor_sync(0xffffffffu, rs0, off);
                        rs1 += __shfl_xor_sync(0xffffffffu, rs1, off);
                    }
                    l[mt][0] = l[mt][0] * sc0 + rs0;
                    l[mt][1] = l[mt][1] * sc1 + rs1;
                    mx[mt][0] = mn0;
                    mx[mt][1] = mn1;
#pragma unroll
                    for (int nt = 0; nt < 8; nt++) {
                        o[mt][nt][0] *= sc0; o[mt][nt][1] *= sc0;
                        o[mt][nt][2] *= sc1; o[mt][nt][3] *= sc1;
                    }
                }

                // ---- O += P V (P regathered via quad shfl) ----
#pragma unroll
                for (int j = 0; j < 8; j++) {
                    unsigned pa[2][4];
#pragma unroll
                    for (int mt = 0; mt < 2; mt++) {
                        const float v00 = __shfl_sync(0xffffffffu, s[mt][j][0], sA);
                        const float v01 = __shfl_sync(0xffffffffu, s[mt][j][1], sA);
                        const float v10 = __shfl_sync(0xffffffffu, s[mt][j][2], sA);
                        const float v11 = __shfl_sync(0xffffffffu, s[mt][j][3], sA);
                        const float w00 = __shfl_sync(0xffffffffu, s[mt][j][0], sB);
                        const float w01 = __shfl_sync(0xffffffffu, s[mt][j][1], sB);
                        const float w10 = __shfl_sync(0xffffffffu, s[mt][j][2], sB);
                        const float w11 = __shfl_sync(0xffffffffu, s[mt][j][3], sB);
                        pa[mt][0] = fu(odd ? v01 : v00);
                        pa[mt][1] = fu(odd ? v11 : v10);
                        pa[mt][2] = fu(odd ? w01 : w00);
                        pa[mt][3] = fu(odd ? w11 : w10);
                    }
                    const int kk = j * 8;
#pragma unroll
                    for (int nt = 0; nt < 8; nt++) {
                        const unsigned b0 = fu(Vc[(kk + tg) * VSS + nt * 8 + g]);
                        const unsigned b1 = fu(Vc[(kk + tg + 4) * VSS + nt * 8 + g]);
                        mma8(o[0][nt], pa[0][0], pa[0][1], pa[0][2], pa[0][3], b0, b1);
                        mma8(o[1][nt], pa[1][0], pa[1][1], pa[1][2], pa[1][3], b0, b1);
                    }
                }
            }

            __syncthreads();   // all warps done with buf kt before it is overwritten
        }

        // ---- normalize + write O[s, h*64+d] ----
#pragma unroll
        for (int mt = 0; mt < 2; mt++) {
            const float inv0 = 1.0f / l[mt][0];
            const float inv1 = 1.0f / l[mt][1];
            const int r0 = q0 + wm + 16 * mt + g;
#pragma unroll
            for (int nt = 0; nt < 8; nt++) {
                const int col = h * HD + nt * 8 + 2 * tg;
                *(float2*)(g_o + (size_t)r0 * D_MODEL + col) =
                    make_float2(o[mt][nt][0] * inv0, o[mt][nt][1] * inv0);
                *(float2*)(g_o + (size_t)(r0 + 8) * D_MODEL + col) =
                    make_float2(o[mt][nt][2] * inv1, o[mt][nt][3] * inv1);
            }
        }
    }
}

// ============================================================
// launch
// ============================================================
extern "C" void kernel_launch(void* const* d_in, const int* in_sizes, int n_in,
                              void* d_out, int out_size)
{
    (void)in_sizes; (void)n_in; (void)out_size;
    const float* x    = (const float*)d_in[0];
    // d_in[1] = attn_mask: pure causal, handled analytically
    const float* cosb = (const float*)d_in[2];
    const float* sinb = (const float*)d_in[3];
    const float* Wqkv = (const float*)d_in[4];
    const float* Wout = (const float*)d_in[5];
    float* out = (float*)d_out;

    void* pqkv = nullptr;
    void* po   = nullptr;
    cudaGetSymbolAddress(&pqkv, g_qkv);
    cudaGetSymbolAddress(&po,   g_o);

    static int attr_set = 0;
    if (!attr_set) {
        cudaFuncSetAttribute(flash_attn_tc2,
                             cudaFuncAttributeMaxDynamicSharedMemorySize,
                             FA_SMEM_BYTES);
        attr_set = 1;
    }

    // 1) qkv = x @ W_qkv
    gemm_tf32<<<dim3(3 * D_MODEL / 128, S_LEN / 128), 256>>>(
        x, Wqkv, (float*)pqkv, S_LEN, 3 * D_MODEL, D_MODEL);

    // 2) RoPE + head-major split (pre-rounded tf32)
    rope_split<<<S_LEN, 256>>>((const float*)pqkv, cosb, sinb);

    // 3) causal flash attention v2
    flash_attn_tc2<<<dim3(16, NHEAD), 128, FA_SMEM_BYTES>>>();

    // 4) out = O @ W_out
    gemm_tf32<<<dim3(D_MODEL / 128, S_LEN / 128), 256>>>(
        (const float*)po, Wout, out, S_LEN, D_MODEL, D_MODEL);
}